// round 2
// baseline (speedup 1.0000x reference)
#include <cuda_runtime.h>
#include <math.h>
#include <float.h>

#define MDIM   4096      // B*S tokens
#define KDIM   1024      // embedding dim
#define VOCABN 32000
#define NBITS  15

// ---------------------------------------------------------------------------
// Kernel 1: id_emb gather + bit_emb (+-1 combination of weight_bit rows)
// grid = 4096 (one CTA per token), 256 threads, 4 floats/thread
// ---------------------------------------------------------------------------
__global__ __launch_bounds__(256) void embed_kernel(
    const int*   __restrict__ ids,
    const float* __restrict__ weight,       // [VOCAB, 1024]
    const float* __restrict__ weight_bit,   // [15, 1024]
    float* __restrict__ out_id,             // [4096, 1024]
    float* __restrict__ out_bit)            // [4096, 1024]
{
    const int t  = blockIdx.x;
    const int id = ids[t];                  // ids are in [0, VOCAB)
    const int d  = threadIdx.x * 4;

    float4 w = *(const float4*)(weight + (size_t)id * KDIM + d);
    *(float4*)(out_id + (size_t)t * KDIM + d) = w;

    float4 acc = make_float4(0.f, 0.f, 0.f, 0.f);
#pragma unroll
    for (int j = 0; j < NBITS; j++) {
        const float s = ((id >> (NBITS - 1 - j)) & 1) ? 1.0f : -1.0f;
        float4 wb = *(const float4*)(weight_bit + j * KDIM + d);
        acc.x = fmaf(s, wb.x, acc.x);
        acc.y = fmaf(s, wb.y, acc.y);
        acc.z = fmaf(s, wb.z, acc.z);
        acc.w = fmaf(s, wb.w, acc.w);
    }
    *(float4*)(out_bit + (size_t)t * KDIM + d) = acc;
}

// ---------------------------------------------------------------------------
// Kernel 2: logit = tensor[4096,1024] @ weight[32000,1024]^T  (fp32 SGEMM NT)
// 128x128 tile, BK=8, 256 threads, 8x8 per-thread microtile, double-buffered.
// grid = (32 Mtiles [fast], 250 Ntiles) so CTAs sharing a weight slice are
// temporally adjacent -> weight slice served from L2 across the 32 M-tiles.
// ---------------------------------------------------------------------------
__global__ __launch_bounds__(256, 2) void sgemm_nt_kernel(
    const float* __restrict__ A,   // [4096, 1024]
    const float* __restrict__ B,   // [32000, 1024]
    float* __restrict__ C)         // [4096, 32000]
{
    __shared__ float As[2][8][132];   // padded to kill STS bank conflicts
    __shared__ float Bs[2][8][132];

    const int tid = threadIdx.x;
    const int tx  = tid & 15;         // 0..15  -> N subtile
    const int ty  = tid >> 4;         // 0..15  -> M subtile
    const int bm  = blockIdx.x * 128;
    const int bn  = blockIdx.y * 128;

    // loader mapping: 256 threads * 1 float4 covers a 128x8 tile
    const int lr = tid >> 1;          // 0..127 (row within tile)
    const int lc = (tid & 1) << 2;    // 0 or 4 (k offset)

    const float* Ap = A + (size_t)(bm + lr) * KDIM + lc;
    const float* Bp = B + (size_t)(bn + lr) * KDIM + lc;

    float4 a4 = *(const float4*)Ap;
    float4 b4 = *(const float4*)Bp;
    As[0][lc + 0][lr] = a4.x; As[0][lc + 1][lr] = a4.y;
    As[0][lc + 2][lr] = a4.z; As[0][lc + 3][lr] = a4.w;
    Bs[0][lc + 0][lr] = b4.x; Bs[0][lc + 1][lr] = b4.y;
    Bs[0][lc + 2][lr] = b4.z; Bs[0][lc + 3][lr] = b4.w;
    __syncthreads();

    float acc[8][8] = {};
    int buf = 0;
    const int NK = KDIM / 8;          // 128 k-tiles

    for (int kt = 0; kt < NK; kt++) {
        if (kt + 1 < NK) {
            a4 = *(const float4*)(Ap + (kt + 1) * 8);
            b4 = *(const float4*)(Bp + (kt + 1) * 8);
        }
#pragma unroll
        for (int k = 0; k < 8; k++) {
            float ar[8], br[8];
            *(float4*)&ar[0] = *(const float4*)&As[buf][k][ty * 8];
            *(float4*)&ar[4] = *(const float4*)&As[buf][k][ty * 8 + 4];
            *(float4*)&br[0] = *(const float4*)&Bs[buf][k][tx * 8];
            *(float4*)&br[4] = *(const float4*)&Bs[buf][k][tx * 8 + 4];
#pragma unroll
            for (int i = 0; i < 8; i++)
#pragma unroll
                for (int j = 0; j < 8; j++)
                    acc[i][j] = fmaf(ar[i], br[j], acc[i][j]);
        }
        if (kt + 1 < NK) {
            buf ^= 1;
            As[buf][lc + 0][lr] = a4.x; As[buf][lc + 1][lr] = a4.y;
            As[buf][lc + 2][lr] = a4.z; As[buf][lc + 3][lr] = a4.w;
            Bs[buf][lc + 0][lr] = b4.x; Bs[buf][lc + 1][lr] = b4.y;
            Bs[buf][lc + 2][lr] = b4.z; Bs[buf][lc + 3][lr] = b4.w;
            __syncthreads();
        }
    }

#pragma unroll
    for (int i = 0; i < 8; i++) {
        float* c = C + (size_t)(bm + ty * 8 + i) * VOCABN + bn + tx * 8;
        *(float4*)(c)     = make_float4(acc[i][0], acc[i][1], acc[i][2], acc[i][3]);
        *(float4*)(c + 4) = make_float4(acc[i][4], acc[i][5], acc[i][6], acc[i][7]);
    }
}

// ---------------------------------------------------------------------------
// Kernel 3: per-row softmax over 32000 logits + 15 bit-masked prob sums.
// logit_w[k] = sum_v p_v * (+-1 bit k of v) = (2*S_k - Z)/Z  with
// S_k = sum_{v: bit set} e_v, Z = sum e_v. One CTA per row, deterministic
// tree reductions (no float atomics).
// ---------------------------------------------------------------------------
__global__ __launch_bounds__(256) void softmax_bits_kernel(
    const float* __restrict__ logit,   // [4096, 32000]
    float* __restrict__ logit_w)       // [4096, 15]
{
    const int row = blockIdx.x;
    const int tid = threadIdx.x;
    const float* x = logit + (size_t)row * VOCABN;

    // pass 1: row max
    float m = -FLT_MAX;
    for (int v = tid; v < VOCABN; v += 256) m = fmaxf(m, x[v]);
#pragma unroll
    for (int o = 16; o; o >>= 1) m = fmaxf(m, __shfl_xor_sync(0xffffffffu, m, o));

    __shared__ float smax[8];
    if ((tid & 31) == 0) smax[tid >> 5] = m;
    __syncthreads();
    float mm = smax[0];
#pragma unroll
    for (int w = 1; w < 8; w++) mm = fmaxf(mm, smax[w]);

    // pass 2: Z and 15 bit sums
    float Z = 0.f, S[NBITS];
#pragma unroll
    for (int k = 0; k < NBITS; k++) S[k] = 0.f;

    for (int v = tid; v < VOCABN; v += 256) {
        const float e = expf(x[v] - mm);
        Z += e;
#pragma unroll
        for (int k = 0; k < NBITS; k++)
            if ((v >> (NBITS - 1 - k)) & 1) S[k] += e;
    }

    // warp-level reduce 16 values
#pragma unroll
    for (int o = 16; o; o >>= 1) {
        Z += __shfl_xor_sync(0xffffffffu, Z, o);
#pragma unroll
        for (int k = 0; k < NBITS; k++)
            S[k] += __shfl_xor_sync(0xffffffffu, S[k], o);
    }

    __shared__ float red[16][8];
    __shared__ float sfin[16];
    if ((tid & 31) == 0) {
        const int w = tid >> 5;
#pragma unroll
        for (int k = 0; k < NBITS; k++) red[k][w] = S[k];
        red[NBITS][w] = Z;
    }
    __syncthreads();
    if (tid < 16) {
        float s = 0.f;
#pragma unroll
        for (int w = 0; w < 8; w++) s += red[tid][w];
        sfin[tid] = s;
    }
    __syncthreads();
    if (tid < NBITS) {
        const float Zt = sfin[NBITS];
        logit_w[(size_t)row * NBITS + tid] = (2.f * sfin[tid] - Zt) / Zt;
    }
}

// ---------------------------------------------------------------------------
// launch: inputs per metadata order: input_ids(int32), tensor(f32),
// weight(f32), weight_bit(f32). Output = concat(id_emb, bit_emb, logit,
// logit_w) flattened f32 (4,194,304 + 4,194,304 + 131,072,000 + 61,440).
// ---------------------------------------------------------------------------
extern "C" void kernel_launch(void* const* d_in, const int* in_sizes, int n_in,
                              void* d_out, int out_size)
{
    const int*   ids        = (const int*)  d_in[0];
    const float* tensor     = (const float*)d_in[1];
    const float* weight     = (const float*)d_in[2];
    const float* weight_bit = (const float*)d_in[3];

    float* out       = (float*)d_out;
    float* out_id    = out;
    float* out_bit   = out + (size_t)MDIM * KDIM;
    float* out_logit = out + (size_t)2 * MDIM * KDIM;
    float* out_lw    = out_logit + (size_t)MDIM * VOCABN;

    embed_kernel<<<MDIM, 256>>>(ids, weight, weight_bit, out_id, out_bit);

    dim3 grid(MDIM / 128, VOCABN / 128);   // M fast -> weight slice L2 reuse
    sgemm_nt_kernel<<<grid, 256>>>(tensor, weight, out_logit);

    softmax_bits_kernel<<<MDIM, 256>>>(out_logit, out_lw);
}

// round 4
// speedup vs baseline: 2.5540x; 2.5540x over previous
#include <cuda_runtime.h>
#include <cuda_bf16.h>
#include <cstdint>
#include <math.h>
#include <float.h>

#define MDIM   4096
#define KDIM   1024
#define VOCABN 32000
#define NBITS  15

// ---------------- scratch: bf16 hi/lo splits --------------------------------
__device__ __nv_bfloat16 g_Ahi[(size_t)MDIM * KDIM];
__device__ __nv_bfloat16 g_Alo[(size_t)MDIM * KDIM];
__device__ __nv_bfloat16 g_Bhi[(size_t)VOCABN * KDIM];
__device__ __nv_bfloat16 g_Blo[(size_t)VOCABN * KDIM];

__device__ __forceinline__ uint32_t smem_u32(const void* p) {
    uint32_t a;
    asm("{ .reg .u64 t; cvta.to.shared.u64 t, %1; cvt.u32.u64 %0, t; }"
        : "=r"(a) : "l"(p));
    return a;
}
#define SW128(o) ((o) ^ (((o) >> 3) & 0x70))

// ---------------- split kernels ---------------------------------------------
__device__ __forceinline__ void split4(float4 v, ushort4& h4, ushort4& l4) {
    __nv_bfloat16 h;
    h = __float2bfloat16(v.x); h4.x = __bfloat16_as_ushort(h);
    l4.x = __bfloat16_as_ushort(__float2bfloat16(v.x - __bfloat162float(h)));
    h = __float2bfloat16(v.y); h4.y = __bfloat16_as_ushort(h);
    l4.y = __bfloat16_as_ushort(__float2bfloat16(v.y - __bfloat162float(h)));
    h = __float2bfloat16(v.z); h4.z = __bfloat16_as_ushort(h);
    l4.z = __bfloat16_as_ushort(__float2bfloat16(v.z - __bfloat162float(h)));
    h = __float2bfloat16(v.w); h4.w = __bfloat16_as_ushort(h);
    l4.w = __bfloat16_as_ushort(__float2bfloat16(v.w - __bfloat162float(h)));
}
__global__ __launch_bounds__(256) void split_A_kernel(const float* __restrict__ src) {
    int i = blockIdx.x * 256 + threadIdx.x;
    ushort4 h4, l4; split4(((const float4*)src)[i], h4, l4);
    ((ushort4*)g_Ahi)[i] = h4; ((ushort4*)g_Alo)[i] = l4;
}
__global__ __launch_bounds__(256) void split_B_kernel(const float* __restrict__ src) {
    int i = blockIdx.x * 256 + threadIdx.x;
    ushort4 h4, l4; split4(((const float4*)src)[i], h4, l4);
    ((ushort4*)g_Bhi)[i] = h4; ((ushort4*)g_Blo)[i] = l4;
}

// ---------------- embed: gather + bit combo ---------------------------------
__global__ __launch_bounds__(256) void embed_kernel(
    const int* __restrict__ ids, const float* __restrict__ weight,
    const float* __restrict__ weight_bit,
    float* __restrict__ out_id, float* __restrict__ out_bit)
{
    const int t = blockIdx.x;
    const int id = ids[t];
    const int d = threadIdx.x * 4;
    float4 w = *(const float4*)(weight + (size_t)id * KDIM + d);
    *(float4*)(out_id + (size_t)t * KDIM + d) = w;
    float4 acc = make_float4(0.f, 0.f, 0.f, 0.f);
#pragma unroll
    for (int j = 0; j < NBITS; j++) {
        const float s = ((id >> (NBITS - 1 - j)) & 1) ? 1.0f : -1.0f;
        float4 wb = *(const float4*)(weight_bit + j * KDIM + d);
        acc.x = fmaf(s, wb.x, acc.x); acc.y = fmaf(s, wb.y, acc.y);
        acc.z = fmaf(s, wb.z, acc.z); acc.w = fmaf(s, wb.w, acc.w);
    }
    *(float4*)(out_bit + (size_t)t * KDIM + d) = acc;
}

// ---------------- bf16x3 GEMM via mma.sync (legacy tensor path) -------------
// C[4096,32000] = A[4096,1024] @ B[32000,1024]^T
// CTA 128x128, BK=64, 3-stage cp.async pipeline, SW128 smem, ldmatrix.x4.
#define BM 128
#define BN 128
#define BK 64
#define NSTAGE 3
#define TILE_B (BM * BK * 2)            // 16 KB (one bf16 tile)
#define STAGE_B (4 * TILE_B)            // Ahi, Alo, Bhi, Blo = 64 KB
#define OFF_ALO TILE_B
#define OFF_BHI (2 * TILE_B)
#define OFF_BLO (3 * TILE_B)
#define GEMM_SMEM (NSTAGE * STAGE_B)    // 192 KB

#define CP16(dst, src) \
    asm volatile("cp.async.cg.shared.global [%0], [%1], 16;" \
                 :: "r"(dst), "l"(src) : "memory")
#define LDSM4(r0, r1, r2, r3, a) \
    asm volatile("ldmatrix.sync.aligned.m8n8.x4.shared.b16 {%0,%1,%2,%3}, [%4];" \
                 : "=r"(r0), "=r"(r1), "=r"(r2), "=r"(r3) : "r"(a))
#define MMA16816(d, a, b0, b1) \
    asm volatile("mma.sync.aligned.m16n8k16.row.col.f32.bf16.bf16.f32 " \
                 "{%0,%1,%2,%3}, {%4,%5,%6,%7}, {%8,%9}, {%0,%1,%2,%3};" \
                 : "+f"((d)[0]), "+f"((d)[1]), "+f"((d)[2]), "+f"((d)[3]) \
                 : "r"((a)[0]), "r"((a)[1]), "r"((a)[2]), "r"((a)[3]), \
                   "r"(b0), "r"(b1))

__global__ __launch_bounds__(256, 1) void gemm_kernel(float* __restrict__ C)
{
    extern __shared__ char smem[];
    const uint32_t sb = smem_u32(smem);
    const int tid = threadIdx.x, wid = tid >> 5, lane = tid & 31;
    const int bm = blockIdx.x * BM, bn = blockIdx.y * BN;
    const int wm = (wid & 1) * 64;      // warp M offset (2 warps in M)
    const int wn = (wid >> 1) * 32;     // warp N offset (4 warps in N)

    const __nv_bfloat16* gAh = g_Ahi + (size_t)bm * KDIM;
    const __nv_bfloat16* gAl = g_Alo + (size_t)bm * KDIM;
    const __nv_bfloat16* gBh = g_Bhi + (size_t)bn * KDIM;
    const __nv_bfloat16* gBl = g_Blo + (size_t)bn * KDIM;

    // loader: 1024 16B-chunks per tile, 256 threads -> 4 chunks/thread/tile
    const int NK = KDIM / BK;           // 16

    auto load_stage = [&](int kt, int stg) {
        const uint32_t base = sb + stg * STAGE_B;
        const int ke = kt * BK;
#pragma unroll
        for (int i = 0; i < 4; i++) {
            const int chunk = i * 256 + tid;
            const int row = chunk >> 3;
            const int kc = chunk & 7;
            const uint32_t d = SW128(row * 128 + kc * 16);
            const size_t so = (size_t)row * KDIM + ke + kc * 8;
            CP16(base + d,           gAh + so);
            CP16(base + OFF_ALO + d, gAl + so);
            CP16(base + OFF_BHI + d, gBh + so);
            CP16(base + OFF_BLO + d, gBl + so);
        }
        asm volatile("cp.async.commit_group;" ::: "memory");
    };

    load_stage(0, 0);
    load_stage(1, 1);

    float acc[4][4][4] = {};            // [mt][nt][frag]

    // per-lane ldmatrix row offsets (bytes within a tile, pre-swizzle)
    const int lrow = lane & 15;
    const int lkb  = (lane >> 4) * 16;
    int offA[4], offB[2];
#pragma unroll
    for (int mt = 0; mt < 4; mt++) offA[mt] = (wm + mt * 16 + lrow) * 128 + lkb;
#pragma unroll
    for (int nt = 0; nt < 2; nt++) offB[nt] = (wn + nt * 16 + lrow) * 128 + lkb;

    for (int kt = 0; kt < NK; kt++) {
        asm volatile("cp.async.wait_group 1;" ::: "memory");
        __syncthreads();
        const uint32_t base = sb + (kt % NSTAGE) * STAGE_B;

#pragma unroll
        for (int ks = 0; ks < 4; ks++) {
            uint32_t ah[4][4], al[4][4], bh[2][4], bl[2][4];
#pragma unroll
            for (int mt = 0; mt < 4; mt++) {
                const uint32_t a = base + SW128(offA[mt] + ks * 32);
                LDSM4(ah[mt][0], ah[mt][1], ah[mt][2], ah[mt][3], a);
                LDSM4(al[mt][0], al[mt][1], al[mt][2], al[mt][3], a + OFF_ALO);
            }
#pragma unroll
            for (int nt = 0; nt < 2; nt++) {
                const uint32_t b = base + SW128(offB[nt] + ks * 32);
                LDSM4(bh[nt][0], bh[nt][1], bh[nt][2], bh[nt][3], b + OFF_BHI);
                LDSM4(bl[nt][0], bl[nt][1], bl[nt][2], bl[nt][3], b + OFF_BLO);
            }
            // x4 B load covers two n8 tiles: frag(2*nt)={r0,r2}, frag(2*nt+1)={r1,r3}
#pragma unroll
            for (int mt = 0; mt < 4; mt++) {
#pragma unroll
                for (int nt = 0; nt < 2; nt++) {
                    MMA16816(acc[mt][2 * nt + 0], ah[mt], bh[nt][0], bh[nt][2]);
                    MMA16816(acc[mt][2 * nt + 1], ah[mt], bh[nt][1], bh[nt][3]);
                    MMA16816(acc[mt][2 * nt + 0], ah[mt], bl[nt][0], bl[nt][2]);
                    MMA16816(acc[mt][2 * nt + 1], ah[mt], bl[nt][1], bl[nt][3]);
                    MMA16816(acc[mt][2 * nt + 0], al[mt], bh[nt][0], bh[nt][2]);
                    MMA16816(acc[mt][2 * nt + 1], al[mt], bh[nt][1], bh[nt][3]);
                }
            }
        }
        __syncthreads();
        if (kt + 2 < NK) load_stage(kt + 2, (kt + 2) % NSTAGE);
    }

    // epilogue: acc frag -> C. rows: lane/4 (+8), cols: (lane%4)*2 (+1)
    const int er = lane >> 2, ec = (lane & 3) * 2;
#pragma unroll
    for (int mt = 0; mt < 4; mt++) {
#pragma unroll
        for (int nt = 0; nt < 4; nt++) {
            float* c0 = C + (size_t)(bm + wm + mt * 16 + er) * VOCABN
                          + bn + wn + nt * 8 + ec;
            *(float2*)c0 = make_float2(acc[mt][nt][0], acc[mt][nt][1]);
            float* c1 = c0 + (size_t)8 * VOCABN;
            *(float2*)c1 = make_float2(acc[mt][nt][2], acc[mt][nt][3]);
        }
    }
}

// ---------------- thresholded softmax + bit projection ----------------------
__global__ __launch_bounds__(256) void softmax_bits_kernel(
    const float* __restrict__ logit, float* __restrict__ logit_w)
{
    const int row = blockIdx.x;
    const int tid = threadIdx.x;
    const float4* x4 = (const float4*)(logit + (size_t)row * VOCABN);

    float m = -FLT_MAX;
    for (int i = tid; i < VOCABN / 4; i += 256) {
        float4 v = x4[i];
        m = fmaxf(m, fmaxf(fmaxf(v.x, v.y), fmaxf(v.z, v.w)));
    }
#pragma unroll
    for (int o = 16; o; o >>= 1) m = fmaxf(m, __shfl_xor_sync(0xffffffffu, m, o));
    __shared__ float smax[8];
    if ((tid & 31) == 0) smax[tid >> 5] = m;
    __syncthreads();
    float mm = smax[0];
#pragma unroll
    for (int w = 1; w < 8; w++) mm = fmaxf(mm, smax[w]);

    const float thr = mm - 20.0f;       // drops <= 32000*e^-20 ~ 7e-5 rel mass
    float Z = 0.f, S[NBITS];
#pragma unroll
    for (int k = 0; k < NBITS; k++) S[k] = 0.f;

    for (int i = tid; i < VOCABN / 4; i += 256) {
        float4 v = x4[i];
        const float c[4] = {v.x, v.y, v.z, v.w};
#pragma unroll
        for (int j = 0; j < 4; j++) {
            if (c[j] > thr) {
                const float e = __expf(c[j] - mm);
                Z += e;
                const int vv = i * 4 + j;
#pragma unroll
                for (int k = 0; k < NBITS; k++)
                    if ((vv >> (NBITS - 1 - k)) & 1) S[k] += e;
            }
        }
    }
#pragma unroll
    for (int o = 16; o; o >>= 1) {
        Z += __shfl_xor_sync(0xffffffffu, Z, o);
#pragma unroll
        for (int k = 0; k < NBITS; k++)
            S[k] += __shfl_xor_sync(0xffffffffu, S[k], o);
    }
    __shared__ float red[16][8];
    __shared__ float sfin[16];
    if ((tid & 31) == 0) {
        const int w = tid >> 5;
#pragma unroll
        for (int k = 0; k < NBITS; k++) red[k][w] = S[k];
        red[NBITS][w] = Z;
    }
    __syncthreads();
    if (tid < 16) {
        float s = 0.f;
#pragma unroll
        for (int w = 0; w < 8; w++) s += red[tid][w];
        sfin[tid] = s;
    }
    __syncthreads();
    if (tid < NBITS) {
        const float Zt = sfin[NBITS];
        logit_w[(size_t)row * NBITS + tid] = (2.f * sfin[tid] - Zt) / Zt;
    }
}

// ---------------- launch ----------------------------------------------------
extern "C" void kernel_launch(void* const* d_in, const int* in_sizes, int n_in,
                              void* d_out, int out_size)
{
    const int*   ids        = (const int*)  d_in[0];
    const float* tensor     = (const float*)d_in[1];
    const float* weight     = (const float*)d_in[2];
    const float* weight_bit = (const float*)d_in[3];

    float* out       = (float*)d_out;
    float* out_id    = out;
    float* out_bit   = out + (size_t)MDIM * KDIM;
    float* out_logit = out + (size_t)2 * MDIM * KDIM;
    float* out_lw    = out_logit + (size_t)MDIM * VOCABN;

    cudaFuncSetAttribute(gemm_kernel,
                         cudaFuncAttributeMaxDynamicSharedMemorySize, GEMM_SMEM);

    embed_kernel<<<MDIM, 256>>>(ids, weight, weight_bit, out_id, out_bit);
    split_A_kernel<<<MDIM * KDIM / 1024, 256>>>(tensor);
    split_B_kernel<<<VOCABN * KDIM / 1024, 256>>>(weight);

    dim3 grid(MDIM / BM, VOCABN / BN);  // M fastest -> B-slice L2 reuse
    gemm_kernel<<<grid, 256, GEMM_SMEM>>>(out_logit);

    softmax_bits_kernel<<<MDIM, 256>>>(out_logit, out_lw);
}

// round 5
// speedup vs baseline: 2.6128x; 1.0230x over previous
#include <cuda_runtime.h>
#include <cuda_bf16.h>
#include <cstdint>
#include <math.h>
#include <float.h>

#define MDIM   4096
#define KDIM   1024
#define VOCABN 32000
#define NBITS  15

// ---------------- scratch: bf16 hi/lo splits --------------------------------
__device__ __nv_bfloat16 g_Ahi[(size_t)MDIM * KDIM];
__device__ __nv_bfloat16 g_Alo[(size_t)MDIM * KDIM];
__device__ __nv_bfloat16 g_Bhi[(size_t)VOCABN * KDIM];
__device__ __nv_bfloat16 g_Blo[(size_t)VOCABN * KDIM];

__device__ __forceinline__ uint32_t smem_u32(const void* p) {
    uint32_t a;
    asm("{ .reg .u64 t; cvta.to.shared.u64 t, %1; cvt.u32.u64 %0, t; }"
        : "=r"(a) : "l"(p));
    return a;
}
#define SW128(o) ((o) ^ (((o) >> 3) & 0x70))

// ---------------- split kernels ---------------------------------------------
__device__ __forceinline__ void split4(float4 v, ushort4& h4, ushort4& l4) {
    __nv_bfloat16 h;
    h = __float2bfloat16(v.x); h4.x = __bfloat16_as_ushort(h);
    l4.x = __bfloat16_as_ushort(__float2bfloat16(v.x - __bfloat162float(h)));
    h = __float2bfloat16(v.y); h4.y = __bfloat16_as_ushort(h);
    l4.y = __bfloat16_as_ushort(__float2bfloat16(v.y - __bfloat162float(h)));
    h = __float2bfloat16(v.z); h4.z = __bfloat16_as_ushort(h);
    l4.z = __bfloat16_as_ushort(__float2bfloat16(v.z - __bfloat162float(h)));
    h = __float2bfloat16(v.w); h4.w = __bfloat16_as_ushort(h);
    l4.w = __bfloat16_as_ushort(__float2bfloat16(v.w - __bfloat162float(h)));
}
__global__ __launch_bounds__(256) void split_A_kernel(const float* __restrict__ src) {
    int i = blockIdx.x * 256 + threadIdx.x;
    ushort4 h4, l4; split4(((const float4*)src)[i], h4, l4);
    ((ushort4*)g_Ahi)[i] = h4; ((ushort4*)g_Alo)[i] = l4;
}
__global__ __launch_bounds__(256) void split_B_kernel(const float* __restrict__ src) {
    int i = blockIdx.x * 256 + threadIdx.x;
    ushort4 h4, l4; split4(((const float4*)src)[i], h4, l4);
    ((ushort4*)g_Bhi)[i] = h4; ((ushort4*)g_Blo)[i] = l4;
}

// ---------------- embed: gather + bit combo ---------------------------------
__global__ __launch_bounds__(256) void embed_kernel(
    const int* __restrict__ ids, const float* __restrict__ weight,
    const float* __restrict__ weight_bit,
    float* __restrict__ out_id, float* __restrict__ out_bit)
{
    const int t = blockIdx.x;
    const int id = ids[t];
    const int d = threadIdx.x * 4;
    float4 w = *(const float4*)(weight + (size_t)id * KDIM + d);
    *(float4*)(out_id + (size_t)t * KDIM + d) = w;
    float4 acc = make_float4(0.f, 0.f, 0.f, 0.f);
#pragma unroll
    for (int j = 0; j < NBITS; j++) {
        const float s = ((id >> (NBITS - 1 - j)) & 1) ? 1.0f : -1.0f;
        float4 wb = *(const float4*)(weight_bit + j * KDIM + d);
        acc.x = fmaf(s, wb.x, acc.x); acc.y = fmaf(s, wb.y, acc.y);
        acc.z = fmaf(s, wb.z, acc.z); acc.w = fmaf(s, wb.w, acc.w);
    }
    *(float4*)(out_bit + (size_t)t * KDIM + d) = acc;
}

// ---------------- bf16x3 GEMM via mma.sync ----------------------------------
// C[4096,32000] = A[4096,1024] @ B[32000,1024]^T
// CTA 128x256, warp tile 64x64 (8 warps, 2Mx4N), BK=64, 2-stage cp.async.
#define BM 128
#define BN 256
#define BK 64
#define NSTAGE 2
#define TILE_A (BM * BK * 2)            // 16 KB
#define TILE_Bt (BN * BK * 2)           // 32 KB
#define OFF_ALO TILE_A                  // 16 KB
#define OFF_BHI (2 * TILE_A)            // 32 KB
#define OFF_BLO (2 * TILE_A + TILE_Bt)  // 64 KB
#define STAGE_B (2 * TILE_A + 2 * TILE_Bt)  // 96 KB
#define GEMM_SMEM (NSTAGE * STAGE_B)        // 192 KB

#define CP16(dst, src) \
    asm volatile("cp.async.cg.shared.global [%0], [%1], 16;" \
                 :: "r"(dst), "l"(src) : "memory")
#define LDSM4(r0, r1, r2, r3, a) \
    asm volatile("ldmatrix.sync.aligned.m8n8.x4.shared.b16 {%0,%1,%2,%3}, [%4];" \
                 : "=r"(r0), "=r"(r1), "=r"(r2), "=r"(r3) : "r"(a))
#define MMA16816(d, a, b0, b1) \
    asm volatile("mma.sync.aligned.m16n8k16.row.col.f32.bf16.bf16.f32 " \
                 "{%0,%1,%2,%3}, {%4,%5,%6,%7}, {%8,%9}, {%0,%1,%2,%3};" \
                 : "+f"((d)[0]), "+f"((d)[1]), "+f"((d)[2]), "+f"((d)[3]) \
                 : "r"((a)[0]), "r"((a)[1]), "r"((a)[2]), "r"((a)[3]), \
                   "r"(b0), "r"(b1))

__global__ __launch_bounds__(256, 1) void gemm_kernel(float* __restrict__ C)
{
    extern __shared__ char smem[];
    const uint32_t sb = smem_u32(smem);
    const int tid = threadIdx.x, wid = tid >> 5, lane = tid & 31;
    const int bm = blockIdx.x * BM, bn = blockIdx.y * BN;
    const int wm = (wid & 1) * 64;      // 2 warps in M
    const int wn = (wid >> 1) * 64;     // 4 warps in N

    const __nv_bfloat16* gAh = g_Ahi + (size_t)bm * KDIM;
    const __nv_bfloat16* gAl = g_Alo + (size_t)bm * KDIM;
    const __nv_bfloat16* gBh = g_Bhi + (size_t)bn * KDIM;
    const __nv_bfloat16* gBl = g_Blo + (size_t)bn * KDIM;

    const int NK = KDIM / BK;           // 16

    auto load_stage = [&](int kt, int stg) {
        const uint32_t base = sb + stg * STAGE_B;
        const int ke = kt * BK;
        // A tiles: 128 rows x 8 chunks = 1024 chunks -> 4 per thread
#pragma unroll
        for (int i = 0; i < 4; i++) {
            const int chunk = i * 256 + tid;
            const int row = chunk >> 3;
            const int kc = chunk & 7;
            const uint32_t d = SW128(row * 128 + kc * 16);
            const size_t so = (size_t)row * KDIM + ke + kc * 8;
            CP16(base + d,           gAh + so);
            CP16(base + OFF_ALO + d, gAl + so);
        }
        // B tiles: 256 rows x 8 chunks = 2048 chunks -> 8 per thread
#pragma unroll
        for (int i = 0; i < 8; i++) {
            const int chunk = i * 256 + tid;
            const int row = chunk >> 3;
            const int kc = chunk & 7;
            const uint32_t d = SW128(row * 128 + kc * 16);
            const size_t so = (size_t)row * KDIM + ke + kc * 8;
            CP16(base + OFF_BHI + d, gBh + so);
            CP16(base + OFF_BLO + d, gBl + so);
        }
        asm volatile("cp.async.commit_group;" ::: "memory");
    };

    load_stage(0, 0);
    load_stage(1, 1);

    float acc[4][8][4] = {};            // [mt 16-row][nt8 8-col][frag]

    const int lrow = lane & 15;
    const int lkb  = (lane >> 4) * 16;
    int offA[4], offB[4];
#pragma unroll
    for (int mt = 0; mt < 4; mt++) offA[mt] = (wm + mt * 16 + lrow) * 128 + lkb;
#pragma unroll
    for (int nt = 0; nt < 4; nt++) offB[nt] = (wn + nt * 16 + lrow) * 128 + lkb;

    for (int kt = 0; kt < NK; kt++) {
        asm volatile("cp.async.wait_group 1;" ::: "memory");
        __syncthreads();
        const uint32_t base = sb + (kt & 1) * STAGE_B;

#pragma unroll
        for (int ks = 0; ks < 4; ks++) {
            uint32_t bh[4][4], bl[4][4];
#pragma unroll
            for (int nt = 0; nt < 4; nt++) {
                const uint32_t b = base + SW128(offB[nt] + ks * 32);
                LDSM4(bh[nt][0], bh[nt][1], bh[nt][2], bh[nt][3], b + OFF_BHI);
                LDSM4(bl[nt][0], bl[nt][1], bl[nt][2], bl[nt][3], b + OFF_BLO);
            }
#pragma unroll
            for (int mt = 0; mt < 4; mt++) {
                uint32_t ah[4], al[4];
                const uint32_t a = base + SW128(offA[mt] + ks * 32);
                LDSM4(ah[0], ah[1], ah[2], ah[3], a);
                LDSM4(al[0], al[1], al[2], al[3], a + OFF_ALO);
#pragma unroll
                for (int nt = 0; nt < 4; nt++) {
                    MMA16816(acc[mt][2 * nt + 0], ah, bh[nt][0], bh[nt][2]);
                    MMA16816(acc[mt][2 * nt + 1], ah, bh[nt][1], bh[nt][3]);
                    MMA16816(acc[mt][2 * nt + 0], ah, bl[nt][0], bl[nt][2]);
                    MMA16816(acc[mt][2 * nt + 1], ah, bl[nt][1], bl[nt][3]);
                    MMA16816(acc[mt][2 * nt + 0], al, bh[nt][0], bh[nt][2]);
                    MMA16816(acc[mt][2 * nt + 1], al, bh[nt][1], bh[nt][3]);
                }
            }
        }
        __syncthreads();
        if (kt + 2 < NK) load_stage(kt + 2, kt & 1);
    }

    // epilogue
    const int er = lane >> 2, ec = (lane & 3) * 2;
#pragma unroll
    for (int mt = 0; mt < 4; mt++) {
#pragma unroll
        for (int nt = 0; nt < 8; nt++) {
            float* c0 = C + (size_t)(bm + wm + mt * 16 + er) * VOCABN
                          + bn + wn + nt * 8 + ec;
            *(float2*)c0 = make_float2(acc[mt][nt][0], acc[mt][nt][1]);
            float* c1 = c0 + (size_t)8 * VOCABN;
            *(float2*)c1 = make_float2(acc[mt][nt][2], acc[mt][nt][3]);
        }
    }
}

// ---------------- thresholded softmax + bit projection ----------------------
__global__ __launch_bounds__(256) void softmax_bits_kernel(
    const float* __restrict__ logit, float* __restrict__ logit_w)
{
    const int row = blockIdx.x;
    const int tid = threadIdx.x;
    const float4* x4 = (const float4*)(logit + (size_t)row * VOCABN);

    float m = -FLT_MAX;
    for (int i = tid; i < VOCABN / 4; i += 256) {
        float4 v = x4[i];
        m = fmaxf(m, fmaxf(fmaxf(v.x, v.y), fmaxf(v.z, v.w)));
    }
#pragma unroll
    for (int o = 16; o; o >>= 1) m = fmaxf(m, __shfl_xor_sync(0xffffffffu, m, o));
    __shared__ float smax[8];
    if ((tid & 31) == 0) smax[tid >> 5] = m;
    __syncthreads();
    float mm = smax[0];
#pragma unroll
    for (int w = 1; w < 8; w++) mm = fmaxf(mm, smax[w]);

    const float thr = mm - 20.0f;       // drops <= 32000*e^-20 ~ 7e-5 rel mass
    float Z = 0.f, S[NBITS];
#pragma unroll
    for (int k = 0; k < NBITS; k++) S[k] = 0.f;

    for (int i = tid; i < VOCABN / 4; i += 256) {
        float4 v = x4[i];
        const float c[4] = {v.x, v.y, v.z, v.w};
#pragma unroll
        for (int j = 0; j < 4; j++) {
            if (c[j] > thr) {
                const float e = __expf(c[j] - mm);
                Z += e;
                const int vv = i * 4 + j;
#pragma unroll
                for (int k = 0; k < NBITS; k++)
                    if ((vv >> (NBITS - 1 - k)) & 1) S[k] += e;
            }
        }
    }
#pragma unroll
    for (int o = 16; o; o >>= 1) {
        Z += __shfl_xor_sync(0xffffffffu, Z, o);
#pragma unroll
        for (int k = 0; k < NBITS; k++)
            S[k] += __shfl_xor_sync(0xffffffffu, S[k], o);
    }
    __shared__ float red[16][8];
    __shared__ float sfin[16];
    if ((tid & 31) == 0) {
        const int w = tid >> 5;
#pragma unroll
        for (int k = 0; k < NBITS; k++) red[k][w] = S[k];
        red[NBITS][w] = Z;
    }
    __syncthreads();
    if (tid < 16) {
        float s = 0.f;
#pragma unroll
        for (int w = 0; w < 8; w++) s += red[tid][w];
        sfin[tid] = s;
    }
    __syncthreads();
    if (tid < NBITS) {
        const float Zt = sfin[NBITS];
        logit_w[(size_t)row * NBITS + tid] = (2.f * sfin[tid] - Zt) / Zt;
    }
}

// ---------------- launch ----------------------------------------------------
extern "C" void kernel_launch(void* const* d_in, const int* in_sizes, int n_in,
                              void* d_out, int out_size)
{
    const int*   ids        = (const int*)  d_in[0];
    const float* tensor     = (const float*)d_in[1];
    const float* weight     = (const float*)d_in[2];
    const float* weight_bit = (const float*)d_in[3];

    float* out       = (float*)d_out;
    float* out_id    = out;
    float* out_bit   = out + (size_t)MDIM * KDIM;
    float* out_logit = out + (size_t)2 * MDIM * KDIM;
    float* out_lw    = out_logit + (size_t)MDIM * VOCABN;

    cudaFuncSetAttribute(gemm_kernel,
                         cudaFuncAttributeMaxDynamicSharedMemorySize, GEMM_SMEM);

    embed_kernel<<<MDIM, 256>>>(ids, weight, weight_bit, out_id, out_bit);
    split_A_kernel<<<MDIM * KDIM / 1024, 256>>>(tensor);
    split_B_kernel<<<VOCABN * KDIM / 1024, 256>>>(weight);

    dim3 grid(MDIM / BM, VOCABN / BN);  // M fastest -> B-slice L2 reuse
    gemm_kernel<<<grid, 256, GEMM_SMEM>>>(out_logit);

    softmax_bits_kernel<<<MDIM, 256>>>(out_logit, out_lw);
}

// round 6
// speedup vs baseline: 2.6688x; 1.0215x over previous
#include <cuda_runtime.h>
#include <cuda_bf16.h>
#include <cstdint>
#include <math.h>
#include <float.h>

#define MDIM   4096
#define KDIM   1024
#define VOCABN 32000
#define NBITS  15

// ---------------- scratch: bf16 hi/lo splits --------------------------------
__device__ __nv_bfloat16 g_Ahi[(size_t)MDIM * KDIM];
__device__ __nv_bfloat16 g_Alo[(size_t)MDIM * KDIM];
__device__ __nv_bfloat16 g_Bhi[(size_t)VOCABN * KDIM];
__device__ __nv_bfloat16 g_Blo[(size_t)VOCABN * KDIM];

__device__ __forceinline__ uint32_t smem_u32(const void* p) {
    uint32_t a;
    asm("{ .reg .u64 t; cvta.to.shared.u64 t, %1; cvt.u32.u64 %0, t; }"
        : "=r"(a) : "l"(p));
    return a;
}
#define SW128(o) ((o) ^ (((o) >> 3) & 0x70))

// ---------------- split kernels ---------------------------------------------
__device__ __forceinline__ void split4(float4 v, ushort4& h4, ushort4& l4) {
    __nv_bfloat16 h;
    h = __float2bfloat16(v.x); h4.x = __bfloat16_as_ushort(h);
    l4.x = __bfloat16_as_ushort(__float2bfloat16(v.x - __bfloat162float(h)));
    h = __float2bfloat16(v.y); h4.y = __bfloat16_as_ushort(h);
    l4.y = __bfloat16_as_ushort(__float2bfloat16(v.y - __bfloat162float(h)));
    h = __float2bfloat16(v.z); h4.z = __bfloat16_as_ushort(h);
    l4.z = __bfloat16_as_ushort(__float2bfloat16(v.z - __bfloat162float(h)));
    h = __float2bfloat16(v.w); h4.w = __bfloat16_as_ushort(h);
    l4.w = __bfloat16_as_ushort(__float2bfloat16(v.w - __bfloat162float(h)));
}
__global__ __launch_bounds__(256) void split_A_kernel(const float* __restrict__ src) {
    int i = blockIdx.x * 256 + threadIdx.x;
    ushort4 h4, l4; split4(((const float4*)src)[i], h4, l4);
    ((ushort4*)g_Ahi)[i] = h4; ((ushort4*)g_Alo)[i] = l4;
}
__global__ __launch_bounds__(256) void split_B_kernel(const float* __restrict__ src) {
    int i = blockIdx.x * 256 + threadIdx.x;
    ushort4 h4, l4; split4(((const float4*)src)[i], h4, l4);
    ((ushort4*)g_Bhi)[i] = h4; ((ushort4*)g_Blo)[i] = l4;
}

// ---------------- embed: gather + bit combo ---------------------------------
__global__ __launch_bounds__(256) void embed_kernel(
    const int* __restrict__ ids, const float* __restrict__ weight,
    const float* __restrict__ weight_bit,
    float* __restrict__ out_id, float* __restrict__ out_bit)
{
    const int t = blockIdx.x;
    const int id = ids[t];
    const int d = threadIdx.x * 4;
    float4 w = *(const float4*)(weight + (size_t)id * KDIM + d);
    *(float4*)(out_id + (size_t)t * KDIM + d) = w;
    float4 acc = make_float4(0.f, 0.f, 0.f, 0.f);
#pragma unroll
    for (int j = 0; j < NBITS; j++) {
        const float s = ((id >> (NBITS - 1 - j)) & 1) ? 1.0f : -1.0f;
        float4 wb = *(const float4*)(weight_bit + j * KDIM + d);
        acc.x = fmaf(s, wb.x, acc.x); acc.y = fmaf(s, wb.y, acc.y);
        acc.z = fmaf(s, wb.z, acc.z); acc.w = fmaf(s, wb.w, acc.w);
    }
    *(float4*)(out_bit + (size_t)t * KDIM + d) = acc;
}

// ---------------- bf16x3 GEMM via mma.sync ----------------------------------
// C[4096,32000] = A[4096,1024] @ B[32000,1024]^T
// CTA 128x256, warp tile 64x64 (8 warps, 2Mx4N), BK=64, 2-stage cp.async.
// Inner loop: 3 passes (hh, lh, hl) over all fragments; b-regs reused between
// BHI and BLO so only one b-set is live -> no spills, no dependent MMA chains.
#define BM 128
#define BN 256
#define BK 64
#define NSTAGE 2
#define TILE_A (BM * BK * 2)            // 16 KB
#define TILE_Bt (BN * BK * 2)           // 32 KB
#define OFF_ALO TILE_A
#define OFF_BHI (2 * TILE_A)
#define OFF_BLO (2 * TILE_A + TILE_Bt)
#define STAGE_B (2 * TILE_A + 2 * TILE_Bt)  // 96 KB
#define GEMM_SMEM (NSTAGE * STAGE_B)        // 192 KB

#define CP16(dst, src) \
    asm volatile("cp.async.cg.shared.global [%0], [%1], 16;" \
                 :: "r"(dst), "l"(src) : "memory")
#define LDSM4(r0, r1, r2, r3, a) \
    asm volatile("ldmatrix.sync.aligned.m8n8.x4.shared.b16 {%0,%1,%2,%3}, [%4];" \
                 : "=r"(r0), "=r"(r1), "=r"(r2), "=r"(r3) : "r"(a))
#define MMA16816(d, a, b0, b1) \
    asm volatile("mma.sync.aligned.m16n8k16.row.col.f32.bf16.bf16.f32 " \
                 "{%0,%1,%2,%3}, {%4,%5,%6,%7}, {%8,%9}, {%0,%1,%2,%3};" \
                 : "+f"((d)[0]), "+f"((d)[1]), "+f"((d)[2]), "+f"((d)[3]) \
                 : "r"((a)[0]), "r"((a)[1]), "r"((a)[2]), "r"((a)[3]), \
                   "r"(b0), "r"(b1))

__global__ __launch_bounds__(256, 1) void gemm_kernel(float* __restrict__ C)
{
    extern __shared__ char smem[];
    const uint32_t sb = smem_u32(smem);
    const int tid = threadIdx.x, wid = tid >> 5, lane = tid & 31;
    const int bm = blockIdx.x * BM, bn = blockIdx.y * BN;
    const int wm = (wid & 1) * 64;
    const int wn = (wid >> 1) * 64;

    const __nv_bfloat16* gAh = g_Ahi + (size_t)bm * KDIM;
    const __nv_bfloat16* gAl = g_Alo + (size_t)bm * KDIM;
    const __nv_bfloat16* gBh = g_Bhi + (size_t)bn * KDIM;
    const __nv_bfloat16* gBl = g_Blo + (size_t)bn * KDIM;

    const int NK = KDIM / BK;           // 16

    auto load_stage = [&](int kt, int stg) {
        const uint32_t base = sb + stg * STAGE_B;
        const int ke = kt * BK;
#pragma unroll
        for (int i = 0; i < 4; i++) {
            const int chunk = i * 256 + tid;
            const int row = chunk >> 3;
            const int kc = chunk & 7;
            const uint32_t d = SW128(row * 128 + kc * 16);
            const size_t so = (size_t)row * KDIM + ke + kc * 8;
            CP16(base + d,           gAh + so);
            CP16(base + OFF_ALO + d, gAl + so);
        }
#pragma unroll
        for (int i = 0; i < 8; i++) {
            const int chunk = i * 256 + tid;
            const int row = chunk >> 3;
            const int kc = chunk & 7;
            const uint32_t d = SW128(row * 128 + kc * 16);
            const size_t so = (size_t)row * KDIM + ke + kc * 8;
            CP16(base + OFF_BHI + d, gBh + so);
            CP16(base + OFF_BLO + d, gBl + so);
        }
        asm volatile("cp.async.commit_group;" ::: "memory");
    };

    load_stage(0, 0);
    load_stage(1, 1);

    float acc[4][8][4] = {};            // 128 regs

    const int lrow = lane & 15;
    const int lkb  = (lane >> 4) * 16;
    int offA[4], offB[4];
#pragma unroll
    for (int mt = 0; mt < 4; mt++) offA[mt] = (wm + mt * 16 + lrow) * 128 + lkb;
#pragma unroll
    for (int nt = 0; nt < 4; nt++) offB[nt] = (wn + nt * 16 + lrow) * 128 + lkb;

    for (int kt = 0; kt < NK; kt++) {
        asm volatile("cp.async.wait_group 1;" ::: "memory");
        __syncthreads();
        const uint32_t base = sb + (kt & 1) * STAGE_B;

#pragma unroll
        for (int ks = 0; ks < 4; ks++) {
            uint32_t ah[4][4], al[4][4];     // 32 regs
#pragma unroll
            for (int mt = 0; mt < 4; mt++) {
                const uint32_t a = base + SW128(offA[mt] + ks * 32);
                LDSM4(ah[mt][0], ah[mt][1], ah[mt][2], ah[mt][3], a);
                LDSM4(al[mt][0], al[mt][1], al[mt][2], al[mt][3], a + OFF_ALO);
            }
            uint32_t b[4][4];                // 16 regs, reused BHI -> BLO
#pragma unroll
            for (int nt = 0; nt < 4; nt++) {
                const uint32_t ba = base + SW128(offB[nt] + ks * 32);
                LDSM4(b[nt][0], b[nt][1], b[nt][2], b[nt][3], ba + OFF_BHI);
            }
            // pass 1: hh — A_hi x B_hi
#pragma unroll
            for (int mt = 0; mt < 4; mt++)
#pragma unroll
                for (int nt = 0; nt < 4; nt++) {
                    MMA16816(acc[mt][2 * nt + 0], ah[mt], b[nt][0], b[nt][2]);
                    MMA16816(acc[mt][2 * nt + 1], ah[mt], b[nt][1], b[nt][3]);
                }
            // pass 2: lh — A_lo x B_hi
#pragma unroll
            for (int mt = 0; mt < 4; mt++)
#pragma unroll
                for (int nt = 0; nt < 4; nt++) {
                    MMA16816(acc[mt][2 * nt + 0], al[mt], b[nt][0], b[nt][2]);
                    MMA16816(acc[mt][2 * nt + 1], al[mt], b[nt][1], b[nt][3]);
                }
            // reload b with B_lo (same registers)
#pragma unroll
            for (int nt = 0; nt < 4; nt++) {
                const uint32_t ba = base + SW128(offB[nt] + ks * 32);
                LDSM4(b[nt][0], b[nt][1], b[nt][2], b[nt][3], ba + OFF_BLO);
            }
            // pass 3: hl — A_hi x B_lo
#pragma unroll
            for (int mt = 0; mt < 4; mt++)
#pragma unroll
                for (int nt = 0; nt < 4; nt++) {
                    MMA16816(acc[mt][2 * nt + 0], ah[mt], b[nt][0], b[nt][2]);
                    MMA16816(acc[mt][2 * nt + 1], ah[mt], b[nt][1], b[nt][3]);
                }
        }
        __syncthreads();
        if (kt + 2 < NK) load_stage(kt + 2, kt & 1);
    }

    // epilogue
    const int er = lane >> 2, ec = (lane & 3) * 2;
#pragma unroll
    for (int mt = 0; mt < 4; mt++) {
#pragma unroll
        for (int nt = 0; nt < 8; nt++) {
            float* c0 = C + (size_t)(bm + wm + mt * 16 + er) * VOCABN
                          + bn + wn + nt * 8 + ec;
            *(float2*)c0 = make_float2(acc[mt][nt][0], acc[mt][nt][1]);
            float* c1 = c0 + (size_t)8 * VOCABN;
            *(float2*)c1 = make_float2(acc[mt][nt][2], acc[mt][nt][3]);
        }
    }
}

// ---------------- thresholded softmax + bit projection ----------------------
__global__ __launch_bounds__(256) void softmax_bits_kernel(
    const float* __restrict__ logit, float* __restrict__ logit_w)
{
    const int row = blockIdx.x;
    const int tid = threadIdx.x;
    const float4* x4 = (const float4*)(logit + (size_t)row * VOCABN);

    float m = -FLT_MAX;
    for (int i = tid; i < VOCABN / 4; i += 256) {
        float4 v = x4[i];
        m = fmaxf(m, fmaxf(fmaxf(v.x, v.y), fmaxf(v.z, v.w)));
    }
#pragma unroll
    for (int o = 16; o; o >>= 1) m = fmaxf(m, __shfl_xor_sync(0xffffffffu, m, o));
    __shared__ float smax[8];
    if ((tid & 31) == 0) smax[tid >> 5] = m;
    __syncthreads();
    float mm = smax[0];
#pragma unroll
    for (int w = 1; w < 8; w++) mm = fmaxf(mm, smax[w]);

    const float thr = mm - 20.0f;
    float Z = 0.f, S[NBITS];
#pragma unroll
    for (int k = 0; k < NBITS; k++) S[k] = 0.f;

    for (int i = tid; i < VOCABN / 4; i += 256) {
        float4 v = x4[i];
        const float c[4] = {v.x, v.y, v.z, v.w};
#pragma unroll
        for (int j = 0; j < 4; j++) {
            if (c[j] > thr) {
                const float e = __expf(c[j] - mm);
                Z += e;
                const int vv = i * 4 + j;
#pragma unroll
                for (int k = 0; k < NBITS; k++)
                    if ((vv >> (NBITS - 1 - k)) & 1) S[k] += e;
            }
        }
    }
#pragma unroll
    for (int o = 16; o; o >>= 1) {
        Z += __shfl_xor_sync(0xffffffffu, Z, o);
#pragma unroll
        for (int k = 0; k < NBITS; k++)
            S[k] += __shfl_xor_sync(0xffffffffu, S[k], o);
    }
    __shared__ float red[16][8];
    __shared__ float sfin[16];
    if ((tid & 31) == 0) {
        const int w = tid >> 5;
#pragma unroll
        for (int k = 0; k < NBITS; k++) red[k][w] = S[k];
        red[NBITS][w] = Z;
    }
    __syncthreads();
    if (tid < 16) {
        float s = 0.f;
#pragma unroll
        for (int w = 0; w < 8; w++) s += red[tid][w];
        sfin[tid] = s;
    }
    __syncthreads();
    if (tid < NBITS) {
        const float Zt = sfin[NBITS];
        logit_w[(size_t)row * NBITS + tid] = (2.f * sfin[tid] - Zt) / Zt;
    }
}

// ---------------- launch ----------------------------------------------------
extern "C" void kernel_launch(void* const* d_in, const int* in_sizes, int n_in,
                              void* d_out, int out_size)
{
    const int*   ids        = (const int*)  d_in[0];
    const float* tensor     = (const float*)d_in[1];
    const float* weight     = (const float*)d_in[2];
    const float* weight_bit = (const float*)d_in[3];

    float* out       = (float*)d_out;
    float* out_id    = out;
    float* out_bit   = out + (size_t)MDIM * KDIM;
    float* out_logit = out + (size_t)2 * MDIM * KDIM;
    float* out_lw    = out_logit + (size_t)MDIM * VOCABN;

    cudaFuncSetAttribute(gemm_kernel,
                         cudaFuncAttributeMaxDynamicSharedMemorySize, GEMM_SMEM);

    embed_kernel<<<MDIM, 256>>>(ids, weight, weight_bit, out_id, out_bit);
    split_A_kernel<<<MDIM * KDIM / 1024, 256>>>(tensor);
    split_B_kernel<<<VOCABN * KDIM / 1024, 256>>>(weight);

    dim3 grid(MDIM / BM, VOCABN / BN);  // M fastest -> B-slice L2 reuse
    gemm_kernel<<<grid, 256, GEMM_SMEM>>>(out_logit);

    softmax_bits_kernel<<<MDIM, 256>>>(out_logit, out_lw);
}